// round 1
// baseline (speedup 1.0000x reference)
#include <cuda_runtime.h>

// DenseAttention via Gram-matrix reassociation (no softmax => pure matrix algebra):
//   G[b,q]  = X_{b,q}^T X_{b,q}                      (X_{b,q} = hidden[b,:,q*256:(q+1)*256], 2048x256)
//   T[b,a,q]= W_{a,q} @ G[b,q]                       (W_{a,q}[e,f] = queries[a,e,q*256+f])
//   Pq[b,a,q]= T[b,a,q] @ C_{a,q}                    (C_{a,q}[g,g'] = combiners[a,q*256+g,g'])
//   P[b,a]  = sum_q Pq[b,a,q]
//   out[b,:,a*256:(a+1)*256] = X_{b,a} @ P[b,a]
// Total ~3.2e9 MACs vs ~7.7e10 for the reference O(S^2) path.

#define S_LEN 2048
#define E_DIM 1024
#define H 256
#define HH (H * H)

// Scratch (static __device__ => no allocation; deterministic, no atomics anywhere)
__device__ float g_Gpart[4 * 8 * HH];  // [chunk][b*4+q][f*H+g]   8 MB
__device__ float g_G[8 * HH];          // [b*4+q]                 2 MB
__device__ float g_T[32 * HH];         // [b*16+a*4+q]            8 MB
__device__ float g_Pq[32 * HH];        // [b*16+a*4+q]            8 MB
__device__ float g_P[8 * HH];          // [b*4+a]                 2 MB

// ---------------------------------------------------------------------------
// Generic 128x128 output-tile GEMM, 256 threads, 8x8 per thread, BK=16.
// AMODE==0: A is K-major  (A[k*lda + m])  -- used for X^T X (Gram)
// AMODE==1: A is M-major  (A[m*lda + k])  -- standard row-major NN GEMM
// B is always K-major row-major (B[k*ldb + n]). C row-major (C[m*ldc + n]).
// All of M,N multiples of 128 and K multiple of 16 in this problem: no guards.
// ---------------------------------------------------------------------------
template <int AMODE>
__device__ __forceinline__ void gemm_tile_128(
    const float* __restrict__ A, int lda,
    const float* __restrict__ B, int ldb,
    float* __restrict__ C, int ldc,
    int K, int tm, int tn)
{
    __shared__ float As[16][132];  // [kk][m], padded vs bank conflicts
    __shared__ float Bs[16][128];  // [kk][n]

    const int tid = threadIdx.x;
    const int tx = tid & 15;        // 0..15 -> col group
    const int ty = tid >> 4;        // 0..15 -> row group
    const int r0 = ty * 8;
    const int c0 = tx * 8;

    float acc[8][8];
#pragma unroll
    for (int i = 0; i < 8; i++)
#pragma unroll
        for (int j = 0; j < 8; j++) acc[i][j] = 0.0f;

    for (int k0 = 0; k0 < K; k0 += 16) {
        // ---- load A tile (128 m x 16 k) into As[kk][m] ----
        if (AMODE == 0) {
            const int col = tid & 127;       // m index, coalesced
            const int kr  = tid >> 7;        // 0..1
#pragma unroll
            for (int i = 0; i < 8; i++) {
                const int kk = kr + 2 * i;
                As[kk][col] = A[(size_t)(k0 + kk) * lda + tm + col];
            }
        } else {
            const int kk = tid & 15;
            const int mr = tid >> 4;         // 0..15
#pragma unroll
            for (int i = 0; i < 8; i++) {
                const int m = mr + 16 * i;
                As[kk][m] = A[(size_t)(tm + m) * lda + k0 + kk];
            }
        }
        // ---- load B tile (16 k x 128 n) into Bs[kk][n], coalesced ----
        {
            const int col = tid & 127;
            const int kr  = tid >> 7;
#pragma unroll
            for (int i = 0; i < 8; i++) {
                const int kk = kr + 2 * i;
                Bs[kk][col] = B[(size_t)(k0 + kk) * ldb + tn + col];
            }
        }
        __syncthreads();

#pragma unroll
        for (int kk = 0; kk < 16; kk++) {
            float a[8], bv[8];
            *(float4*)&a[0]  = *(const float4*)&As[kk][r0];
            *(float4*)&a[4]  = *(const float4*)&As[kk][r0 + 4];
            *(float4*)&bv[0] = *(const float4*)&Bs[kk][c0];
            *(float4*)&bv[4] = *(const float4*)&Bs[kk][c0 + 4];
#pragma unroll
            for (int i = 0; i < 8; i++)
#pragma unroll
                for (int j = 0; j < 8; j++)
                    acc[i][j] = fmaf(a[i], bv[j], acc[i][j]);
        }
        __syncthreads();
    }

    // ---- store 8x8 per thread as float4s ----
#pragma unroll
    for (int i = 0; i < 8; i++) {
        float4 v0 = make_float4(acc[i][0], acc[i][1], acc[i][2], acc[i][3]);
        float4 v1 = make_float4(acc[i][4], acc[i][5], acc[i][6], acc[i][7]);
        float* crow = C + (size_t)(tm + r0 + i) * ldc + tn + c0;
        *(float4*)&crow[0] = v0;
        *(float4*)&crow[4] = v1;
    }
}

// ---------------------------------------------------------------------------
// Stage 1: Gram partials. G_{b,q} = X^T X split over 4 K-chunks of 512 rows.
// grid: x = tile (2x2 of 128), y = chunk (4), z = bq (8)
// ---------------------------------------------------------------------------
__global__ __launch_bounds__(256, 2)
void k_gram(const float* __restrict__ hidden)
{
    const int tile  = blockIdx.x;
    const int tm    = (tile >> 1) * 128;
    const int tn    = (tile & 1) * 128;
    const int chunk = blockIdx.y;
    const int bq    = blockIdx.z;
    const int b     = bq >> 2;
    const int q     = bq & 3;

    const float* X = hidden + (size_t)b * S_LEN * E_DIM + q * H
                            + (size_t)chunk * 512 * E_DIM;
    float* out = g_Gpart + ((size_t)chunk * 8 + bq) * HH;
    gemm_tile_128<0>(X, E_DIM, X, E_DIM, out, H, 512, tm, tn);
}

// Stage 1b: reduce 4 chunk partials -> G.  524288 elements.
__global__ void k_reduceG()
{
    const int idx = blockIdx.x * 256 + threadIdx.x;   // grid 2048 x 256
    const int CS = 8 * HH;                            // 524288
    g_G[idx] = g_Gpart[idx] + g_Gpart[idx + CS] + g_Gpart[idx + 2 * CS]
             + g_Gpart[idx + 3 * CS];
}

// ---------------------------------------------------------------------------
// Stage 2: T[b,a,q] = W_{a,q} @ G[b,q].  grid: x = tile(4), z = baq(32)
// ---------------------------------------------------------------------------
__global__ __launch_bounds__(256, 2)
void k_wg(const float* __restrict__ queries)
{
    const int tile = blockIdx.x;
    const int tm   = (tile >> 1) * 128;
    const int tn   = (tile & 1) * 128;
    const int baq  = blockIdx.z;
    const int b = baq >> 4, a = (baq >> 2) & 3, q = baq & 3;

    const float* W = queries + (size_t)a * 262144 + q * H;   // W[e,f] @ e*1024+f
    const float* G = g_G + (size_t)(b * 4 + q) * HH;
    float* T = g_T + (size_t)baq * HH;
    gemm_tile_128<1>(W, 1024, G, H, T, H, H, tm, tn);
}

// ---------------------------------------------------------------------------
// Stage 3: Pq[b,a,q] = T[b,a,q] @ C_{a,q}.  grid: x = tile(4), z = baq(32)
// ---------------------------------------------------------------------------
__global__ __launch_bounds__(256, 2)
void k_pq(const float* __restrict__ combiners)
{
    const int tile = blockIdx.x;
    const int tm   = (tile >> 1) * 128;
    const int tn   = (tile & 1) * 128;
    const int baq  = blockIdx.z;
    const int a = (baq >> 2) & 3, q = baq & 3;

    const float* T  = g_T + (size_t)baq * HH;
    const float* Cq = combiners + (size_t)a * 262144 + q * HH;  // [g,g'] @ g*256+g'
    float* out = g_Pq + (size_t)baq * HH;
    gemm_tile_128<1>(T, H, Cq, H, out, H, H, tm, tn);
}

// Stage 3b: P[b,a] = sum_q Pq.  524288 elements.
__global__ void k_reduceP()
{
    const int idx = blockIdx.x * 256 + threadIdx.x;   // grid 2048 x 256
    const int ba  = idx >> 16;
    const int off = idx & 65535;
    float s = 0.0f;
#pragma unroll
    for (int q = 0; q < 4; q++)
        s += g_Pq[((size_t)(ba * 4 + q) << 16) + off];
    g_P[idx] = s;
}

// ---------------------------------------------------------------------------
// Stage 4: out[b,:,a*256:+256] = X_{b,a} @ P[b,a].  grid: x = tiles(32), z = ba(8)
// ---------------------------------------------------------------------------
__global__ __launch_bounds__(256, 2)
void k_out(const float* __restrict__ hidden, float* __restrict__ out)
{
    const int tile = blockIdx.x;
    const int tm   = (tile >> 1) * 128;   // 0..15 -> 2048 rows
    const int tn   = (tile & 1) * 128;
    const int ba   = blockIdx.z;
    const int b = ba >> 2, a = ba & 3;

    const float* X = hidden + (size_t)b * S_LEN * E_DIM + a * H;  // M-major lda=1024
    const float* P = g_P + (size_t)ba * HH;
    float* O = out + (size_t)b * S_LEN * E_DIM + a * H;
    gemm_tile_128<1>(X, E_DIM, P, H, O, E_DIM, H, tm, tn);
}

// ---------------------------------------------------------------------------
extern "C" void kernel_launch(void* const* d_in, const int* in_sizes, int n_in,
                              void* d_out, int out_size)
{
    const float* hidden    = (const float*)d_in[0];  // [2,2048,1024]
    const float* queries   = (const float*)d_in[1];  // [4,256,1024]
    const float* combiners = (const float*)d_in[2];  // [4,1024,256]
    float* out = (float*)d_out;                      // [2,2048,1024]

    (void)in_sizes; (void)n_in; (void)out_size;

    k_gram<<<dim3(4, 4, 8), 256>>>(hidden);
    k_reduceG<<<2048, 256>>>();
    k_wg<<<dim3(4, 1, 32), 256>>>(queries);
    k_pq<<<dim3(4, 1, 32), 256>>>(combiners);
    k_reduceP<<<2048, 256>>>();
    k_out<<<dim3(32, 1, 8), 256>>>(hidden, out);
}

// round 3
// speedup vs baseline: 1.9137x; 1.9137x over previous
#include <cuda_runtime.h>
#include <cuda_bf16.h>
#include <cstdint>

// ============================================================================
// DenseAttention via Gram reassociation (validated in R1, rel_err 7e-7 fp32):
//   G[b,q]  = X_{b,q}^T X_{b,q}
//   T[b,a,q]= W_{a,q} @ G[b,q]
//   Pq      = T @ C_{a,q};  P[b,a] = sum_q Pq
//   out     = X_{b,a} @ P[b,a]
// Executed with HMMA (mma.sync bf16) + hi/lo error splitting:
//   x = hi + lo (bf16 each);  A·B ~= AhBh + AhBl + AlBh  (fp32 accum)
// Baseline PTX only (mma.sync / ldmatrix / cp.async) — assembles on compute_103.
// ============================================================================

#define HID_B 2
#define HID_S 2048
#define HID_E 1024
#define H 256
#define HH 65536

// ---------------- scratch (static device globals; no allocation) ------------
__device__ __align__(256) __nv_bfloat16 g_Xt_h[8 * H * HID_S];   // [bq][f][t]
__device__ __align__(256) __nv_bfloat16 g_Xt_l[8 * H * HID_S];
__device__ __align__(256) __nv_bfloat16 g_Xnt_h[HID_B * HID_S * HID_E];
__device__ __align__(256) __nv_bfloat16 g_Xnt_l[HID_B * HID_S * HID_E];
__device__ __align__(256) __nv_bfloat16 g_Wc_h[16 * HH];          // [aq][e][f]
__device__ __align__(256) __nv_bfloat16 g_Wc_l[16 * HH];
__device__ __align__(256) __nv_bfloat16 g_Ct_h[16 * HH];          // [aq][g'][g]
__device__ __align__(256) __nv_bfloat16 g_Ct_l[16 * HH];
__device__ __align__(256) float         g_Gpart[8 * 8 * HH];      // [chunk][bq]
__device__ __align__(256) __nv_bfloat16 g_Gh[8 * HH];             // [bq][f][g]
__device__ __align__(256) __nv_bfloat16 g_Gl[8 * HH];
__device__ __align__(256) __nv_bfloat16 g_Th[32 * HH];            // [baq][e][g]
__device__ __align__(256) __nv_bfloat16 g_Tl[32 * HH];
__device__ __align__(256) float         g_Pq[32 * HH];            // [baq][e][g']
__device__ __align__(256) __nv_bfloat16 g_Pt_h[8 * HH];           // [ba][g'][e]
__device__ __align__(256) __nv_bfloat16 g_Pt_l[8 * HH];

// ---------------- PTX helpers (baseline, sm_80-class) ------------------------
__device__ __forceinline__ uint32_t smem_u32(const void* p) {
    uint32_t a;
    asm("{ .reg .u64 t; cvta.to.shared.u64 t, %1; cvt.u32.u64 %0, t; }" : "=r"(a) : "l"(p));
    return a;
}
__device__ __forceinline__ void cpa16(uint32_t s, const void* g) {
    asm volatile("cp.async.cg.shared.global [%0], [%1], 16;" :: "r"(s), "l"(g));
}
#define CP_COMMIT() asm volatile("cp.async.commit_group;" ::: "memory")
#define CP_WAIT(n)  asm volatile("cp.async.wait_group %0;" :: "n"(n) : "memory")

#define LDSM_X4(r, addr) \
    asm volatile("ldmatrix.sync.aligned.m8n8.x4.shared.b16 {%0,%1,%2,%3}, [%4];" \
        : "=r"((r)[0]), "=r"((r)[1]), "=r"((r)[2]), "=r"((r)[3]) : "r"(addr))

#define MMA_BF16(d, a, b0, b1) \
    asm volatile("mma.sync.aligned.m16n8k16.row.col.f32.bf16.bf16.f32 " \
        "{%0,%1,%2,%3}, {%4,%5,%6,%7}, {%8,%9}, {%0,%1,%2,%3};" \
        : "+f"((d)[0]), "+f"((d)[1]), "+f"((d)[2]), "+f"((d)[3]) \
        : "r"((a)[0]), "r"((a)[1]), "r"((a)[2]), "r"((a)[3]), "r"(b0), "r"(b1))

// ---------------- split helpers ----------------------------------------------
__device__ __forceinline__ void split1(float x, __nv_bfloat16& h, __nv_bfloat16& l) {
    h = __float2bfloat16(x);
    l = __float2bfloat16(x - __bfloat162float(h));
}
__device__ __forceinline__ void split4(float4 v, uint2& uh, uint2& ul) {
    union { __nv_bfloat16 b[4]; uint2 u; } Hq, Lq;
    float f[4] = {v.x, v.y, v.z, v.w};
#pragma unroll
    for (int i = 0; i < 4; i++) split1(f[i], Hq.b[i], Lq.b[i]);
    uh = Hq.u; ul = Lq.u;
}

// ============================================================================
// 128x128 tile GEMM body, K = 256 (4 chunks of 64), double-buffered cp.async.
// A: row-major [m][k] (lda), B: [n][k] row-major (ldb)  => mma row.col.
// 8 warps: 4 (M) x 2 (N); warp tile 32x64.
// SMEM per buffer: Ah[128][72] Al Bh Bl  (72 bf16 = 144B padded rows)
// EPI 0: fp32 -> Cf.  EPI 1: bf16 hi/lo -> Ch/Cl.
// ============================================================================
#define ROWB   144                      // padded row bytes (64*2 + 16)
#define T_A_H  0
#define T_A_L  18432
#define T_B_H  36864
#define T_B_L  55296
#define BUFSZ  73728
#define SMEM_DYN (2 * BUFSZ)

template <int EPI>
__device__ __forceinline__ void gemm_body(
    const __nv_bfloat16* __restrict__ Ah, const __nv_bfloat16* __restrict__ Al, int lda,
    const __nv_bfloat16* __restrict__ Bh, const __nv_bfloat16* __restrict__ Bl, int ldb,
    float* __restrict__ Cf,
    __nv_bfloat16* __restrict__ Ch, __nv_bfloat16* __restrict__ Cl, int ldc)
{
    extern __shared__ char smem[];
    const uint32_t sb  = smem_u32(smem);
    const int tid  = threadIdx.x;
    const int lane = tid & 31;
    const int wid  = tid >> 5;
    const int m0   = (wid >> 1) * 32;   // warp M offset within 128
    const int n0   = (wid & 1) * 64;    // warp N offset within 128

    // per-thread ldmatrix base offsets (within a buffer)
    const uint32_t aoff = (uint32_t)(m0 + (lane & 15)) * ROWB + ((lane >> 4) << 4);
    const uint32_t boff = (uint32_t)(n0 + ((lane >> 4) << 3) + (lane & 7)) * ROWB
                        + ((lane & 8) ? 16u : 0u);

    float acc[2][8][4];
#pragma unroll
    for (int i = 0; i < 2; i++)
#pragma unroll
        for (int j = 0; j < 8; j++)
#pragma unroll
            for (int r = 0; r < 4; r++) acc[i][j][r] = 0.0f;

    auto load_chunk = [&](int c) {
        const uint32_t bo = sb + (uint32_t)(c & 1) * BUFSZ;
        const int k0 = c << 6;
#pragma unroll
        for (int i = 0; i < 4; i++) {
            int v = i * 256 + tid;
            int r = v >> 3, j = v & 7;
            uint32_t so = (uint32_t)r * ROWB + (uint32_t)j * 16;
            cpa16(bo + T_A_H + so, Ah + (size_t)r * lda + k0 + j * 8);
            cpa16(bo + T_A_L + so, Al + (size_t)r * lda + k0 + j * 8);
            cpa16(bo + T_B_H + so, Bh + (size_t)r * ldb + k0 + j * 8);
            cpa16(bo + T_B_L + so, Bl + (size_t)r * ldb + k0 + j * 8);
        }
    };

    load_chunk(0);
    CP_COMMIT();

#pragma unroll 1
    for (int c = 0; c < 4; c++) {
        if (c < 3) { load_chunk(c + 1); CP_COMMIT(); CP_WAIT(1); }
        else       { CP_WAIT(0); }
        __syncthreads();

        const uint32_t bo = sb + (uint32_t)(c & 1) * BUFSZ;
        const uint32_t aH = bo + T_A_H + aoff;
        const uint32_t aL = bo + T_A_L + aoff;
        const uint32_t bH = bo + T_B_H + boff;
        const uint32_t bL = bo + T_B_L + boff;

#pragma unroll
        for (int ks = 0; ks < 4; ks++) {
            const uint32_t ko = (uint32_t)ks * 32;
            uint32_t ah0[4], ah1[4], al0[4], al1[4];
            LDSM_X4(ah0, aH + ko);
            LDSM_X4(ah1, aH + 16 * ROWB + ko);
            LDSM_X4(al0, aL + ko);
            LDSM_X4(al1, aL + 16 * ROWB + ko);
            uint32_t bhr[4][4], blr[4][4];
#pragma unroll
            for (int p = 0; p < 4; p++) {
                LDSM_X4(bhr[p], bH + (uint32_t)p * 16 * ROWB + ko);
                LDSM_X4(blr[p], bL + (uint32_t)p * 16 * ROWB + ko);
            }
#pragma unroll
            for (int j = 0; j < 8; j++) {
                const int p = j >> 1, o = (j & 1) * 2;
                MMA_BF16(acc[0][j], ah0, bhr[p][o], bhr[p][o + 1]);
                MMA_BF16(acc[0][j], ah0, blr[p][o], blr[p][o + 1]);
                MMA_BF16(acc[0][j], al0, bhr[p][o], bhr[p][o + 1]);
                MMA_BF16(acc[1][j], ah1, bhr[p][o], bhr[p][o + 1]);
                MMA_BF16(acc[1][j], ah1, blr[p][o], blr[p][o + 1]);
                MMA_BF16(acc[1][j], al1, bhr[p][o], bhr[p][o + 1]);
            }
        }
        __syncthreads();
    }

    // ---- epilogue: c-frag -> gmem ----
    const int rr = lane >> 2;            // 0..7
    const int cc = (lane & 3) * 2;       // 0,2,4,6
#pragma unroll
    for (int i = 0; i < 2; i++) {
#pragma unroll
        for (int j = 0; j < 8; j++) {
            const int row = m0 + i * 16 + rr;
            const int col = n0 + j * 8 + cc;
            if (EPI == 0) {
                float* p = Cf + (size_t)row * ldc + col;
                *(float2*)p = make_float2(acc[i][j][0], acc[i][j][1]);
                *(float2*)(p + (size_t)8 * ldc) = make_float2(acc[i][j][2], acc[i][j][3]);
            } else {
                __nv_bfloat16 h0, l0, h1, l1;
                split1(acc[i][j][0], h0, l0); split1(acc[i][j][1], h1, l1);
                *(__nv_bfloat162*)(Ch + (size_t)row * ldc + col) = __nv_bfloat162(h0, h1);
                *(__nv_bfloat162*)(Cl + (size_t)row * ldc + col) = __nv_bfloat162(l0, l1);
                split1(acc[i][j][2], h0, l0); split1(acc[i][j][3], h1, l1);
                *(__nv_bfloat162*)(Ch + (size_t)(row + 8) * ldc + col) = __nv_bfloat162(h0, h1);
                *(__nv_bfloat162*)(Cl + (size_t)(row + 8) * ldc + col) = __nv_bfloat162(l0, l1);
            }
        }
    }
}

// ============================================================================
// conversion / reduction kernels
// ============================================================================
__global__ void conv_nt(const float* __restrict__ hid)
{
    int idx = blockIdx.x * 256 + threadIdx.x;       // 1M float4s
    float4 v = ((const float4*)hid)[idx];
    uint2 uh, ul;
    split4(v, uh, ul);
    ((uint2*)g_Xnt_h)[idx] = uh;
    ((uint2*)g_Xnt_l)[idx] = ul;
}

__global__ void conv_t(const float* __restrict__ hid)
{
    __shared__ float t[32][33];
    int bq = blockIdx.z, b = bq >> 2, q = bq & 3;
    int t0 = blockIdx.y * 32, f0 = blockIdx.x * 32;
    int tx = threadIdx.x & 31, ty = threadIdx.x >> 5;
#pragma unroll
    for (int r = 0; r < 4; r++) {
        int tt = t0 + ty + r * 8;
        t[ty + r * 8][tx] = hid[(size_t)b * 2097152 + (size_t)tt * 1024 + q * 256 + f0 + tx];
    }
    __syncthreads();
#pragma unroll
    for (int r = 0; r < 4; r++) {
        int f = f0 + ty + r * 8;
        int tw = t0 + tx;
        __nv_bfloat16 h, l;
        split1(t[tx][ty + r * 8], h, l);
        size_t o = (size_t)bq * 524288 + (size_t)f * 2048 + tw;
        g_Xt_h[o] = h; g_Xt_l[o] = l;
    }
}

__global__ void conv_w(const float* __restrict__ qr)
{
    int o4 = blockIdx.x * 256 + threadIdx.x;        // 262144 float4s
    int aq = o4 >> 14;
    int rem = (o4 << 2) & 65535;
    int e = rem >> 8, f = rem & 255;
    int a = aq >> 2, q = aq & 3;
    float4 v = *(const float4*)(qr + (size_t)a * 262144 + (size_t)e * 1024 + q * 256 + f);
    uint2 uh, ul;
    split4(v, uh, ul);
    ((uint2*)g_Wc_h)[o4] = uh;
    ((uint2*)g_Wc_l)[o4] = ul;
}

__global__ void conv_c(const float* __restrict__ cb)
{
    __shared__ float t[32][33];
    int aq = blockIdx.z, a = aq >> 2, q = aq & 3;
    int g0 = blockIdx.y * 32, gp0 = blockIdx.x * 32;
    int tx = threadIdx.x & 31, ty = threadIdx.x >> 5;
#pragma unroll
    for (int r = 0; r < 4; r++) {
        int g = g0 + ty + r * 8;
        t[ty + r * 8][tx] = cb[(size_t)a * 262144 + (size_t)(q * 256 + g) * 256 + gp0 + tx];
    }
    __syncthreads();
#pragma unroll
    for (int r = 0; r < 4; r++) {
        int gp = gp0 + ty + r * 8;
        int gw = g0 + tx;
        __nv_bfloat16 h, l;
        split1(t[tx][ty + r * 8], h, l);
        size_t o = (size_t)aq * 65536 + (size_t)gp * 256 + gw;
        g_Ct_h[o] = h; g_Ct_l[o] = l;
    }
}

__global__ void k_reduceG()
{
    int i4 = blockIdx.x * 256 + threadIdx.x;        // 131072 float4s of G
    float4 s = make_float4(0.f, 0.f, 0.f, 0.f);
#pragma unroll
    for (int c = 0; c < 8; c++) {
        float4 v = ((const float4*)g_Gpart)[(size_t)c * 131072 + i4];
        s.x += v.x; s.y += v.y; s.z += v.z; s.w += v.w;
    }
    uint2 uh, ul;
    split4(s, uh, ul);
    ((uint2*)g_Gh)[i4] = uh;
    ((uint2*)g_Gl)[i4] = ul;
}

__global__ void k_reduceP()
{
    __shared__ float t[32][33];
    int ba = blockIdx.z, b = ba >> 2, a = ba & 3;
    int e0 = blockIdx.y * 32, gp0 = blockIdx.x * 32;
    int tx = threadIdx.x & 31, ty = threadIdx.x >> 5;
#pragma unroll
    for (int r = 0; r < 4; r++) {
        int e = e0 + ty + r * 8;
        float s = 0.f;
#pragma unroll
        for (int q = 0; q < 4; q++)
            s += g_Pq[(size_t)(b * 16 + a * 4 + q) * 65536 + (size_t)e * 256 + gp0 + tx];
        t[ty + r * 8][tx] = s;
    }
    __syncthreads();
#pragma unroll
    for (int r = 0; r < 4; r++) {
        int gp = gp0 + ty + r * 8;
        int ew = e0 + tx;
        __nv_bfloat16 h, l;
        split1(t[tx][ty + r * 8], h, l);
        size_t o = (size_t)ba * 65536 + (size_t)gp * 256 + ew;
        g_Pt_h[o] = h; g_Pt_l[o] = l;
    }
}

// ============================================================================
// GEMM stage kernels (K = 256 each; tiles baked into pointers)
// ============================================================================
__global__ void __launch_bounds__(256, 1)
k_s1()  // Gram split-K: grid (tile 4 = 2x2, chunk 8, bq 8)
{
    int mt = blockIdx.x >> 1, nt = blockIdx.x & 1;
    int ch = blockIdx.y, bq = blockIdx.z;
    size_t xo = (size_t)bq * 524288;
    const __nv_bfloat16* Ah = g_Xt_h + xo + (size_t)mt * 128 * 2048 + ch * 256;
    const __nv_bfloat16* Al = g_Xt_l + xo + (size_t)mt * 128 * 2048 + ch * 256;
    const __nv_bfloat16* Bh = g_Xt_h + xo + (size_t)nt * 128 * 2048 + ch * 256;
    const __nv_bfloat16* Bl = g_Xt_l + xo + (size_t)nt * 128 * 2048 + ch * 256;
    float* Cf = g_Gpart + (size_t)(ch * 8 + bq) * 65536 + (size_t)mt * 128 * 256 + nt * 128;
    gemm_body<0>(Ah, Al, 2048, Bh, Bl, 2048, Cf, nullptr, nullptr, 256);
}

__global__ void __launch_bounds__(256, 1)
k_s2()  // T = W @ G: grid (tile 4, 1, baq 32); G symmetric => B = G rows
{
    int mt = blockIdx.x >> 1, nt = blockIdx.x & 1;
    int baq = blockIdx.z;
    int b = baq >> 4, a = (baq >> 2) & 3, q = baq & 3;
    const __nv_bfloat16* Ah = g_Wc_h + (size_t)(a * 4 + q) * 65536 + (size_t)mt * 128 * 256;
    const __nv_bfloat16* Al = g_Wc_l + (size_t)(a * 4 + q) * 65536 + (size_t)mt * 128 * 256;
    const __nv_bfloat16* Bh = g_Gh + (size_t)(b * 4 + q) * 65536 + (size_t)nt * 128 * 256;
    const __nv_bfloat16* Bl = g_Gl + (size_t)(b * 4 + q) * 65536 + (size_t)nt * 128 * 256;
    __nv_bfloat16* Ch = g_Th + (size_t)baq * 65536 + (size_t)mt * 128 * 256 + nt * 128;
    __nv_bfloat16* Cl = g_Tl + (size_t)baq * 65536 + (size_t)mt * 128 * 256 + nt * 128;
    gemm_body<1>(Ah, Al, 256, Bh, Bl, 256, nullptr, Ch, Cl, 256);
}

__global__ void __launch_bounds__(256, 1)
k_s3()  // Pq = T @ C: grid (tile 4, 1, baq 32)
{
    int mt = blockIdx.x >> 1, nt = blockIdx.x & 1;
    int baq = blockIdx.z;
    int a = (baq >> 2) & 3, q = baq & 3;
    const __nv_bfloat16* Ah = g_Th + (size_t)baq * 65536 + (size_t)mt * 128 * 256;
    const __nv_bfloat16* Al = g_Tl + (size_t)baq * 65536 + (size_t)mt * 128 * 256;
    const __nv_bfloat16* Bh = g_Ct_h + (size_t)(a * 4 + q) * 65536 + (size_t)nt * 128 * 256;
    const __nv_bfloat16* Bl = g_Ct_l + (size_t)(a * 4 + q) * 65536 + (size_t)nt * 128 * 256;
    float* Cf = g_Pq + (size_t)baq * 65536 + (size_t)mt * 128 * 256 + nt * 128;
    gemm_body<0>(Ah, Al, 256, Bh, Bl, 256, Cf, nullptr, nullptr, 256);
}

__global__ void __launch_bounds__(256, 1)
k_s4(float* __restrict__ out)  // out = X @ P: grid (tile 32 = 16x2, 1, ba 8)
{
    int mt = blockIdx.x >> 1, nt = blockIdx.x & 1;
    int ba = blockIdx.z;
    int b = ba >> 2, a = ba & 3;
    const __nv_bfloat16* Ah = g_Xnt_h + (size_t)b * 2097152 + (size_t)mt * 128 * 1024 + a * 256;
    const __nv_bfloat16* Al = g_Xnt_l + (size_t)b * 2097152 + (size_t)mt * 128 * 1024 + a * 256;
    const __nv_bfloat16* Bh = g_Pt_h + (size_t)ba * 65536 + (size_t)nt * 128 * 256;
    const __nv_bfloat16* Bl = g_Pt_l + (size_t)ba * 65536 + (size_t)nt * 128 * 256;
    float* Cf = out + (size_t)b * 2097152 + (size_t)mt * 128 * 1024 + a * 256 + nt * 128;
    gemm_body<0>(Ah, Al, 1024, Bh, Bl, 256, Cf, nullptr, nullptr, 1024);
}

// ============================================================================
extern "C" void kernel_launch(void* const* d_in, const int* in_sizes, int n_in,
                              void* d_out, int out_size)
{
    const float* hidden    = (const float*)d_in[0];  // [2,2048,1024]
    const float* queries   = (const float*)d_in[1];  // [4,256,1024]
    const float* combiners = (const float*)d_in[2];  // [4,1024,256]
    float* out = (float*)d_out;
    (void)in_sizes; (void)n_in; (void)out_size;

    cudaFuncSetAttribute(k_s1, cudaFuncAttributeMaxDynamicSharedMemorySize, SMEM_DYN);
    cudaFuncSetAttribute(k_s2, cudaFuncAttributeMaxDynamicSharedMemorySize, SMEM_DYN);
    cudaFuncSetAttribute(k_s3, cudaFuncAttributeMaxDynamicSharedMemorySize, SMEM_DYN);
    cudaFuncSetAttribute(k_s4, cudaFuncAttributeMaxDynamicSharedMemorySize, SMEM_DYN);

    conv_nt<<<4096, 256>>>(hidden);
    conv_t<<<dim3(8, 64, 8), 256>>>(hidden);
    conv_w<<<1024, 256>>>(queries);
    conv_c<<<dim3(8, 8, 16), 256>>>(combiners);

    k_s1<<<dim3(4, 8, 8), 256, SMEM_DYN>>>();
    k_reduceG<<<512, 256>>>();
    k_s2<<<dim3(4, 1, 32), 256, SMEM_DYN>>>();
    k_s3<<<dim3(4, 1, 32), 256, SMEM_DYN>>>();
    k_reduceP<<<dim3(8, 8, 8), 256>>>();
    k_s4<<<dim3(32, 1, 8), 256, SMEM_DYN>>>(out);
}

// round 4
// speedup vs baseline: 2.5538x; 1.3345x over previous
#include <cuda_runtime.h>
#include <cuda_fp16.h>
#include <cstdint>

// ============================================================================
// DenseAttention via Gram reassociation:
//   G[b,q]  = X_{b,q}^T X_{b,q}
//   T[b,a,q]= (1024*W_{a,q}) @ G[b,q]
//   Pq^T    = (1024*C_{a,q})^T-layout @ T^T ;  P^T[b,a] = 2^-10 * sum_q Pq^T
//   out     = 2^-10 * X_{b,a} @ P[b,a]
// fp16 2-pass split: B = Bh + Bl (fp16 each), A = Ah only:
//   A*B ~= Ah*Bh + Ah*Bl   (fp32 accumulate; dropped Al*B ~ 2.8e-4 rms/stage)
// W,C scaled by 2^10 so their lo-splits stay in fp16 normal range.
// ============================================================================

#define HH 65536

// ---------------- scratch (static device globals; no allocation) ------------
__device__ __align__(256) __half g_Xt_h[8 * 256 * 2048];    // [bq][f][t]
__device__ __align__(256) __half g_Xt_l[8 * 256 * 2048];
__device__ __align__(256) __half g_Xnt_h[2 * 2048 * 1024];  // [b][t][e]
__device__ __align__(256) __half g_Wc_h[16 * HH];           // [aq][e][f] *1024
__device__ __align__(256) __half g_Ct_h[16 * HH];           // [aq][g'][g] *1024
__device__ __align__(256) float  g_Gpart[4 * 8 * HH];       // [chunk][bq][f][g]
__device__ __align__(256) __half g_Gh[8 * HH];              // [bq][f][g]
__device__ __align__(256) __half g_Gl[8 * HH];
__device__ __align__(256) __half g_Th[32 * HH];             // [baq][e][g]
__device__ __align__(256) __half g_Tl[32 * HH];
__device__ __align__(256) float  g_Pq[32 * HH];             // [baq][g'][e]
__device__ __align__(256) __half g_Pt_h[8 * HH];            // [ba][g'][e]
__device__ __align__(256) __half g_Pt_l[8 * HH];

// ---------------- PTX helpers ------------------------------------------------
__device__ __forceinline__ uint32_t smem_u32(const void* p) {
    uint32_t a;
    asm("{ .reg .u64 t; cvta.to.shared.u64 t, %1; cvt.u32.u64 %0, t; }" : "=r"(a) : "l"(p));
    return a;
}
__device__ __forceinline__ void cpa16(uint32_t s, const void* g) {
    asm volatile("cp.async.cg.shared.global [%0], [%1], 16;" :: "r"(s), "l"(g));
}
#define CP_COMMIT() asm volatile("cp.async.commit_group;" ::: "memory")
#define CP_WAIT(n)  asm volatile("cp.async.wait_group %0;" :: "n"(n) : "memory")

#define LDSM_X4(r, addr) \
    asm volatile("ldmatrix.sync.aligned.m8n8.x4.shared.b16 {%0,%1,%2,%3}, [%4];" \
        : "=r"((r)[0]), "=r"((r)[1]), "=r"((r)[2]), "=r"((r)[3]) : "r"(addr))

#define MMA_F16(d, a, b0, b1) \
    asm volatile("mma.sync.aligned.m16n8k16.row.col.f32.f16.f16.f32 " \
        "{%0,%1,%2,%3}, {%4,%5,%6,%7}, {%8,%9}, {%0,%1,%2,%3};" \
        : "+f"((d)[0]), "+f"((d)[1]), "+f"((d)[2]), "+f"((d)[3]) \
        : "r"((a)[0]), "r"((a)[1]), "r"((a)[2]), "r"((a)[3]), "r"(b0), "r"(b1))

// ---------------- split helpers ----------------------------------------------
__device__ __forceinline__ void splitH(float x, __half& h, __half& l) {
    h = __float2half_rn(x);
    l = __float2half_rn(x - __half2float(h));
}
__device__ __forceinline__ void split4H(float4 v, uint2& uh, uint2& ul) {
    union { __half b[4]; uint2 u; } Hq, Lq;
    float f[4] = {v.x, v.y, v.z, v.w};
#pragma unroll
    for (int i = 0; i < 4; i++) splitH(f[i], Hq.b[i], Lq.b[i]);
    uh = Hq.u; ul = Lq.u;
}
__device__ __forceinline__ uint2 pack4H(float4 v) {
    union { __half b[4]; uint2 u; } Hq;
    Hq.b[0] = __float2half_rn(v.x); Hq.b[1] = __float2half_rn(v.y);
    Hq.b[2] = __float2half_rn(v.z); Hq.b[3] = __float2half_rn(v.w);
    return Hq.u;
}

// ============================================================================
// 128x128 tile GEMM, K multiple of 64, double-buffered cp.async, fp16 2-pass.
// A: [m][k] row-major (hi only).  B: [n][k] row-major (hi + lo).
// 8 warps: 4(M) x 2(N); warp tile 32x64.
// EPI 0: fp32*scale -> Cf.   EPI 1: fp16 hi/lo -> Ch/Cl.
// ============================================================================
#define ROWB   144
#define T_A_H  0
#define T_B_H  18432
#define T_B_L  36864
#define BUFSZ  55296
#define SMEM_DYN (2 * BUFSZ)

template <int EPI>
__device__ __forceinline__ void gemm_body(
    const __half* __restrict__ Ah, int lda,
    const __half* __restrict__ Bh, const __half* __restrict__ Bl, int ldb,
    int K, float* __restrict__ Cf,
    __half* __restrict__ Ch, __half* __restrict__ Cl, int ldc, float outScale)
{
    extern __shared__ char smem[];
    const uint32_t sb  = smem_u32(smem);
    const int tid  = threadIdx.x;
    const int lane = tid & 31;
    const int wid  = tid >> 5;
    const int m0   = (wid >> 1) * 32;
    const int n0   = (wid & 1) * 64;

    const uint32_t aoff = (uint32_t)(m0 + (lane & 15)) * ROWB + ((lane >> 4) << 4);
    const uint32_t boff = (uint32_t)(n0 + ((lane >> 4) << 3) + (lane & 7)) * ROWB
                        + ((lane & 8) ? 16u : 0u);

    float acc[2][8][4];
#pragma unroll
    for (int i = 0; i < 2; i++)
#pragma unroll
        for (int j = 0; j < 8; j++)
#pragma unroll
            for (int r = 0; r < 4; r++) acc[i][j][r] = 0.0f;

    auto load_chunk = [&](int c) {
        const uint32_t bo = sb + (uint32_t)(c & 1) * BUFSZ;
        const int k0 = c << 6;
#pragma unroll
        for (int i = 0; i < 4; i++) {
            int v = i * 256 + tid;
            int r = v >> 3, j = v & 7;
            uint32_t so = (uint32_t)r * ROWB + (uint32_t)j * 16;
            cpa16(bo + T_A_H + so, Ah + (size_t)r * lda + k0 + j * 8);
            cpa16(bo + T_B_H + so, Bh + (size_t)r * ldb + k0 + j * 8);
            cpa16(bo + T_B_L + so, Bl + (size_t)r * ldb + k0 + j * 8);
        }
    };

    const int NC = K >> 6;
    load_chunk(0);
    CP_COMMIT();

#pragma unroll 1
    for (int c = 0; c < NC; c++) {
        if (c < NC - 1) { load_chunk(c + 1); CP_COMMIT(); CP_WAIT(1); }
        else            { CP_WAIT(0); }
        __syncthreads();

        const uint32_t bo = sb + (uint32_t)(c & 1) * BUFSZ;
        const uint32_t aH = bo + T_A_H + aoff;
        const uint32_t bH = bo + T_B_H + boff;
        const uint32_t bL = bo + T_B_L + boff;

#pragma unroll
        for (int ks = 0; ks < 4; ks++) {
            const uint32_t ko = (uint32_t)ks * 32;
            uint32_t ah0[4], ah1[4];
            LDSM_X4(ah0, aH + ko);
            LDSM_X4(ah1, aH + 16 * ROWB + ko);
            uint32_t bhr[4][4], blr[4][4];
#pragma unroll
            for (int p = 0; p < 4; p++) {
                LDSM_X4(bhr[p], bH + (uint32_t)p * 16 * ROWB + ko);
                LDSM_X4(blr[p], bL + (uint32_t)p * 16 * ROWB + ko);
            }
#pragma unroll
            for (int j = 0; j < 8; j++) {
                const int p = j >> 1, o = (j & 1) * 2;
                MMA_F16(acc[0][j], ah0, bhr[p][o], bhr[p][o + 1]);
                MMA_F16(acc[0][j], ah0, blr[p][o], blr[p][o + 1]);
                MMA_F16(acc[1][j], ah1, bhr[p][o], bhr[p][o + 1]);
                MMA_F16(acc[1][j], ah1, blr[p][o], blr[p][o + 1]);
            }
        }
        __syncthreads();
    }

    // ---- epilogue ----
    const int rr = lane >> 2;
    const int cc = (lane & 3) * 2;
#pragma unroll
    for (int i = 0; i < 2; i++) {
#pragma unroll
        for (int j = 0; j < 8; j++) {
            const int row = m0 + i * 16 + rr;
            const int col = n0 + j * 8 + cc;
            if (EPI == 0) {
                float* p = Cf + (size_t)row * ldc + col;
                *(float2*)p = make_float2(acc[i][j][0] * outScale, acc[i][j][1] * outScale);
                *(float2*)(p + (size_t)8 * ldc) =
                    make_float2(acc[i][j][2] * outScale, acc[i][j][3] * outScale);
            } else {
                __half h0, l0, h1, l1;
                splitH(acc[i][j][0], h0, l0); splitH(acc[i][j][1], h1, l1);
                *(__half2*)(Ch + (size_t)row * ldc + col) = __halves2half2(h0, h1);
                *(__half2*)(Cl + (size_t)row * ldc + col) = __halves2half2(l0, l1);
                splitH(acc[i][j][2], h0, l0); splitH(acc[i][j][3], h1, l1);
                *(__half2*)(Ch + (size_t)(row + 8) * ldc + col) = __halves2half2(h0, h1);
                *(__half2*)(Cl + (size_t)(row + 8) * ldc + col) = __halves2half2(l0, l1);
            }
        }
    }
}

// ============================================================================
// fused conversion kernel: grid 10240 blocks x 256
//   [0,4096)      : Xnt hi            (hidden, natural layout)
//   [4096,8192)   : Xt hi+lo          (hidden, transposed per (b,q))
//   [8192,9216)   : Wc hi *1024
//   [9216,10240)  : Ct hi *1024       (combiners, transposed per (a,q))
// ============================================================================
__global__ void k_conv(const float* __restrict__ hid,
                       const float* __restrict__ qr,
                       const float* __restrict__ cb)
{
    __shared__ float ts[32][33];
    const int blk = blockIdx.x;
    const int tid = threadIdx.x;

    if (blk < 4096) {
        int idx = blk * 256 + tid;                       // 1M float4s
        float4 v = ((const float4*)hid)[idx];
        ((uint2*)g_Xnt_h)[idx] = pack4H(v);
    } else if (blk < 8192) {
        int i = blk - 4096;                              // 8 x 64 x 8
        int fb = i & 7, tb = (i >> 3) & 63, bq = i >> 9;
        int b = bq >> 2, q = bq & 3;
        int t0 = tb * 32, f0 = fb * 32;
        int tx = tid & 31, ty = tid >> 5;
#pragma unroll
        for (int r = 0; r < 4; r++) {
            int tt = t0 + ty + r * 8;
            ts[ty + r * 8][tx] = hid[(size_t)b * 2097152 + (size_t)tt * 1024 + q * 256 + f0 + tx];
        }
        __syncthreads();
#pragma unroll
        for (int r = 0; r < 4; r++) {
            int f = f0 + ty + r * 8;
            int tw = t0 + tx;
            __half h, l;
            splitH(ts[tx][ty + r * 8], h, l);
            size_t o = (size_t)bq * 524288 + (size_t)f * 2048 + tw;
            g_Xt_h[o] = h; g_Xt_l[o] = l;
        }
    } else if (blk < 9216) {
        int o4 = (blk - 8192) * 256 + tid;               // 262144 float4s
        int aq = o4 >> 14;
        int rem = (o4 << 2) & 65535;
        int e = rem >> 8, f = rem & 255;
        int a = aq >> 2, q = aq & 3;
        float4 v = *(const float4*)(qr + (size_t)a * 262144 + (size_t)e * 1024 + q * 256 + f);
        v.x *= 1024.f; v.y *= 1024.f; v.z *= 1024.f; v.w *= 1024.f;
        ((uint2*)g_Wc_h)[o4] = pack4H(v);
    } else {
        int i = blk - 9216;                              // 8 x 8 x 16
        int gpb = i & 7, gb = (i >> 3) & 7, aq = i >> 6;
        int a = aq >> 2, q = aq & 3;
        int g0 = gb * 32, gp0 = gpb * 32;
        int tx = tid & 31, ty = tid >> 5;
#pragma unroll
        for (int r = 0; r < 4; r++) {
            int g = g0 + ty + r * 8;
            ts[ty + r * 8][tx] =
                cb[(size_t)a * 262144 + (size_t)(q * 256 + g) * 256 + gp0 + tx] * 1024.f;
        }
        __syncthreads();
#pragma unroll
        for (int r = 0; r < 4; r++) {
            int gp = gp0 + ty + r * 8;
            int gw = g0 + tx;
            g_Ct_h[(size_t)aq * 65536 + (size_t)gp * 256 + gw] =
                __float2half_rn(ts[tx][ty + r * 8]);
        }
    }
}

// ---- reduce Gram partials (4 chunks) + split to fp16 hi/lo ------------------
__global__ void k_reduceG()
{
    int i4 = blockIdx.x * 256 + threadIdx.x;             // 131072 float4s
    float4 s = make_float4(0.f, 0.f, 0.f, 0.f);
#pragma unroll
    for (int c = 0; c < 4; c++) {
        float4 v = ((const float4*)g_Gpart)[(size_t)c * 131072 + i4];
        s.x += v.x; s.y += v.y; s.z += v.z; s.w += v.w;
    }
    uint2 uh, ul;
    split4H(s, uh, ul);
    ((uint2*)g_Gh)[i4] = uh;
    ((uint2*)g_Gl)[i4] = ul;
}

// ---- reduce Pq^T over q, descale 2^-10, split to fp16 hi/lo (elementwise) ---
__global__ void k_reduceP()
{
    int i4 = blockIdx.x * 256 + threadIdx.x;             // 131072 float4s of P^T
    int ba = i4 >> 14;                                   // [ba][g'][e]
    int off = i4 & 16383;
    int b = ba >> 2, a = ba & 3;
    size_t base = (size_t)(b * 16 + a * 4) * 16384 + off;
    float4 s = make_float4(0.f, 0.f, 0.f, 0.f);
#pragma unroll
    for (int q = 0; q < 4; q++) {
        float4 v = ((const float4*)g_Pq)[base + (size_t)q * 16384];
        s.x += v.x; s.y += v.y; s.z += v.z; s.w += v.w;
    }
    const float ds = 1.0f / 1024.0f;
    s.x *= ds; s.y *= ds; s.z *= ds; s.w *= ds;
    uint2 uh, ul;
    split4H(s, uh, ul);
    ((uint2*)g_Pt_h)[i4] = uh;
    ((uint2*)g_Pt_l)[i4] = ul;
}

// ============================================================================
// GEMM stage kernels
// ============================================================================
__global__ void __launch_bounds__(256, 1)
k_s1()  // Gram split-K: grid (tile 4 = 2x2, chunk 4, bq 8); K=512 per CTA
{
    int mt = blockIdx.x >> 1, nt = blockIdx.x & 1;
    int ch = blockIdx.y, bq = blockIdx.z;
    size_t xo = (size_t)bq * 524288;
    const __half* Ah = g_Xt_h + xo + (size_t)mt * 128 * 2048 + ch * 512;
    const __half* Bh = g_Xt_h + xo + (size_t)nt * 128 * 2048 + ch * 512;
    const __half* Bl = g_Xt_l + xo + (size_t)nt * 128 * 2048 + ch * 512;
    float* Cf = g_Gpart + (size_t)(ch * 8 + bq) * 65536 + (size_t)mt * 128 * 256 + nt * 128;
    gemm_body<0>(Ah, 2048, Bh, Bl, 2048, 512, Cf, nullptr, nullptr, 256, 1.0f);
}

__global__ void __launch_bounds__(256, 1)
k_s2()  // T = Ws @ G: grid (tile 4, 1, baq 32); G symmetric
{
    int mt = blockIdx.x >> 1, nt = blockIdx.x & 1;
    int baq = blockIdx.z;
    int b = baq >> 4, a = (baq >> 2) & 3, q = baq & 3;
    const __half* Ah = g_Wc_h + (size_t)(a * 4 + q) * 65536 + (size_t)mt * 128 * 256;
    const __half* Bh = g_Gh + (size_t)(b * 4 + q) * 65536 + (size_t)nt * 128 * 256;
    const __half* Bl = g_Gl + (size_t)(b * 4 + q) * 65536 + (size_t)nt * 128 * 256;
    __half* Ch = g_Th + (size_t)baq * 65536 + (size_t)mt * 128 * 256 + nt * 128;
    __half* Cl = g_Tl + (size_t)baq * 65536 + (size_t)mt * 128 * 256 + nt * 128;
    gemm_body<1>(Ah, 256, Bh, Bl, 256, 256, nullptr, Ch, Cl, 256, 1.0f);
}

__global__ void __launch_bounds__(256, 1)
k_s3()  // Pq^T = Cs_t @ T^T : A=Ct[g'][g] hi, B=T[e][g] hi/lo -> out [g'][e]
{
    int mt = blockIdx.x >> 1, nt = blockIdx.x & 1;
    int baq = blockIdx.z;
    int a = (baq >> 2) & 3, q = baq & 3;
    const __half* Ah = g_Ct_h + (size_t)(a * 4 + q) * 65536 + (size_t)mt * 128 * 256;
    const __half* Bh = g_Th + (size_t)baq * 65536 + (size_t)nt * 128 * 256;
    const __half* Bl = g_Tl + (size_t)baq * 65536 + (size_t)nt * 128 * 256;
    float* Cf = g_Pq + (size_t)baq * 65536 + (size_t)mt * 128 * 256 + nt * 128;
    gemm_body<0>(Ah, 256, Bh, Bl, 256, 256, Cf, nullptr, nullptr, 256, 1.0f);
}

__global__ void __launch_bounds__(256, 1)
k_s4(float* __restrict__ out)  // out = 2^-10 * X @ P: grid (tile 32, 1, ba 8)
{
    int mt = blockIdx.x >> 1, nt = blockIdx.x & 1;
    int ba = blockIdx.z;
    int b = ba >> 2, a = ba & 3;
    const __half* Ah = g_Xnt_h + (size_t)b * 2097152 + (size_t)mt * 128 * 1024 + a * 256;
    const __half* Bh = g_Pt_h + (size_t)ba * 65536 + (size_t)nt * 128 * 256;
    const __half* Bl = g_Pt_l + (size_t)ba * 65536 + (size_t)nt * 128 * 256;
    float* Cf = out + (size_t)b * 2097152 + (size_t)mt * 128 * 1024 + a * 256 + nt * 128;
    gemm_body<0>(Ah, 1024, Bh, Bl, 256, 256, Cf, nullptr, nullptr, 1024, 1.0f / 1024.0f);
}

// ============================================================================
extern "C" void kernel_launch(void* const* d_in, const int* in_sizes, int n_in,
                              void* d_out, int out_size)
{
    const float* hidden    = (const float*)d_in[0];  // [2,2048,1024]
    const float* queries   = (const float*)d_in[1];  // [4,256,1024]
    const float* combiners = (const float*)d_in[2];  // [4,1024,256]
    float* out = (float*)d_out;
    (void)in_sizes; (void)n_in; (void)out_size;

    cudaFuncSetAttribute(k_s1, cudaFuncAttributeMaxDynamicSharedMemorySize, SMEM_DYN);
    cudaFuncSetAttribute(k_s2, cudaFuncAttributeMaxDynamicSharedMemorySize, SMEM_DYN);
    cudaFuncSetAttribute(k_s3, cudaFuncAttributeMaxDynamicSharedMemorySize, SMEM_DYN);
    cudaFuncSetAttribute(k_s4, cudaFuncAttributeMaxDynamicSharedMemorySize, SMEM_DYN);

    k_conv<<<10240, 256>>>(hidden, queries, combiners);
    k_s1<<<dim3(4, 4, 8), 256, SMEM_DYN>>>();
    k_reduceG<<<512, 256>>>();
    k_s2<<<dim3(4, 1, 32), 256, SMEM_DYN>>>();
    k_s3<<<dim3(4, 1, 32), 256, SMEM_DYN>>>();
    k_reduceP<<<512, 256>>>();
    k_s4<<<dim3(32, 1, 8), 256, SMEM_DYN>>>(out);
}

// round 5
// speedup vs baseline: 2.6549x; 1.0396x over previous
#include <cuda_runtime.h>
#include <cuda_fp16.h>
#include <cstdint>

// ============================================================================
// DenseAttention via Gram reassociation:
//   G[b,q]  = X_{b,q}^T X_{b,q}             (symmetric => compute 3 of 4 tiles)
//   T[b,a,q]= (1024*W_{a,q}) @ G[b,q]
//   Pq^T    = (1024*C_{a,q})-layout @ T^T ;  P^T[b,a] = 2^-10 * sum_q Pq^T
//   out     = 2^-10 * X_{b,a} @ P[b,a]
// fp16 2-pass split: B = Bh + Bl, A = Ah:  A*B ~= Ah*Bh + Ah*Bl  (fp32 accum)
// MMA issue order groups independent accumulators (dep distance 16).
// ============================================================================

#define HH 65536

// ---------------- scratch (static device globals; no allocation) ------------
__device__ __align__(256) __half g_Xt_h[8 * 256 * 2048];    // [bq][f][t]
__device__ __align__(256) __half g_Xt_l[8 * 256 * 2048];
__device__ __align__(256) __half g_Xnt_h[2 * 2048 * 1024];  // [b][t][e]
__device__ __align__(256) __half g_Wc_h[16 * HH];           // [aq][e][f] *1024
__device__ __align__(256) __half g_Ct_h[16 * HH];           // [aq][g'][g] *1024
__device__ __align__(256) float  g_Gpart[6 * 8 * 3 * 16384];// [chunk][bq][tile]
__device__ __align__(256) __half g_Gh[8 * HH];              // [bq][f][g]
__device__ __align__(256) __half g_Gl[8 * HH];
__device__ __align__(256) __half g_Th[32 * HH];             // [baq][e][g]
__device__ __align__(256) __half g_Tl[32 * HH];
__device__ __align__(256) float  g_Pq[32 * HH];             // [baq][g'][e]
__device__ __align__(256) __half g_Pt_h[8 * HH];            // [ba][g'][e]
__device__ __align__(256) __half g_Pt_l[8 * HH];

// ---------------- PTX helpers ------------------------------------------------
__device__ __forceinline__ uint32_t smem_u32(const void* p) {
    uint32_t a;
    asm("{ .reg .u64 t; cvta.to.shared.u64 t, %1; cvt.u32.u64 %0, t; }" : "=r"(a) : "l"(p));
    return a;
}
__device__ __forceinline__ void cpa16(uint32_t s, const void* g) {
    asm volatile("cp.async.cg.shared.global [%0], [%1], 16;" :: "r"(s), "l"(g));
}
#define CP_COMMIT() asm volatile("cp.async.commit_group;" ::: "memory")
#define CP_WAIT(n)  asm volatile("cp.async.wait_group %0;" :: "n"(n) : "memory")

#define LDSM_X4(r, addr) \
    asm volatile("ldmatrix.sync.aligned.m8n8.x4.shared.b16 {%0,%1,%2,%3}, [%4];" \
        : "=r"((r)[0]), "=r"((r)[1]), "=r"((r)[2]), "=r"((r)[3]) : "r"(addr))

#define MMA_F16(d, a, b0, b1) \
    asm volatile("mma.sync.aligned.m16n8k16.row.col.f32.f16.f16.f32 " \
        "{%0,%1,%2,%3}, {%4,%5,%6,%7}, {%8,%9}, {%0,%1,%2,%3};" \
        : "+f"((d)[0]), "+f"((d)[1]), "+f"((d)[2]), "+f"((d)[3]) \
        : "r"((a)[0]), "r"((a)[1]), "r"((a)[2]), "r"((a)[3]), "r"(b0), "r"(b1))

// ---------------- split helpers ----------------------------------------------
__device__ __forceinline__ void splitH(float x, __half& h, __half& l) {
    h = __float2half_rn(x);
    l = __float2half_rn(x - __half2float(h));
}
__device__ __forceinline__ void split4H(float4 v, uint2& uh, uint2& ul) {
    union { __half b[4]; uint2 u; } Hq, Lq;
    float f[4] = {v.x, v.y, v.z, v.w};
#pragma unroll
    for (int i = 0; i < 4; i++) splitH(f[i], Hq.b[i], Lq.b[i]);
    uh = Hq.u; ul = Lq.u;
}
__device__ __forceinline__ uint2 pack4H(float4 v) {
    union { __half b[4]; uint2 u; } Hq;
    Hq.b[0] = __float2half_rn(v.x); Hq.b[1] = __float2half_rn(v.y);
    Hq.b[2] = __float2half_rn(v.z); Hq.b[3] = __float2half_rn(v.w);
    return Hq.u;
}

// ============================================================================
// 128x128 tile GEMM, K multiple of 64, double-buffered cp.async, fp16 2-pass.
// A: [m][k] row-major (hi only).  B: [n][k] row-major (hi + lo).
// 8 warps: 4(M) x 2(N); warp tile 32x64.
// MMA issue: 4 groups of 8 independent MMAs (hi i0, hi i1, lo i0, lo i1).
// EPI 0: fp32*scale -> Cf.   EPI 1: fp16 hi/lo -> Ch/Cl.
// ============================================================================
#define ROWB   144
#define T_A_H  0
#define T_B_H  18432
#define T_B_L  36864
#define BUFSZ  55296
#define SMEM_DYN (2 * BUFSZ)

template <int EPI>
__device__ __forceinline__ void gemm_body(
    const __half* __restrict__ Ah, int lda,
    const __half* __restrict__ Bh, const __half* __restrict__ Bl, int ldb,
    int K, float* __restrict__ Cf,
    __half* __restrict__ Ch, __half* __restrict__ Cl, int ldc, float outScale)
{
    extern __shared__ char smem[];
    const uint32_t sb  = smem_u32(smem);
    const int tid  = threadIdx.x;
    const int lane = tid & 31;
    const int wid  = tid >> 5;
    const int m0   = (wid >> 1) * 32;
    const int n0   = (wid & 1) * 64;

    const uint32_t aoff = (uint32_t)(m0 + (lane & 15)) * ROWB + ((lane >> 4) << 4);
    const uint32_t boff = (uint32_t)(n0 + ((lane >> 4) << 3) + (lane & 7)) * ROWB
                        + ((lane & 8) ? 16u : 0u);

    float acc[2][8][4];
#pragma unroll
    for (int i = 0; i < 2; i++)
#pragma unroll
        for (int j = 0; j < 8; j++)
#pragma unroll
            for (int r = 0; r < 4; r++) acc[i][j][r] = 0.0f;

    auto load_chunk = [&](int c) {
        const uint32_t bo = sb + (uint32_t)(c & 1) * BUFSZ;
        const int k0 = c << 6;
#pragma unroll
        for (int i = 0; i < 4; i++) {
            int v = i * 256 + tid;
            int r = v >> 3, j = v & 7;
            uint32_t so = (uint32_t)r * ROWB + (uint32_t)j * 16;
            cpa16(bo + T_A_H + so, Ah + (size_t)r * lda + k0 + j * 8);
            cpa16(bo + T_B_H + so, Bh + (size_t)r * ldb + k0 + j * 8);
            cpa16(bo + T_B_L + so, Bl + (size_t)r * ldb + k0 + j * 8);
        }
    };

    const int NC = K >> 6;
    load_chunk(0);
    CP_COMMIT();

#pragma unroll 1
    for (int c = 0; c < NC; c++) {
        if (c < NC - 1) { load_chunk(c + 1); CP_COMMIT(); CP_WAIT(1); }
        else            { CP_WAIT(0); }
        __syncthreads();

        const uint32_t bo = sb + (uint32_t)(c & 1) * BUFSZ;
        const uint32_t aH = bo + T_A_H + aoff;
        const uint32_t bH = bo + T_B_H + boff;
        const uint32_t bL = bo + T_B_L + boff;

#pragma unroll
        for (int ks = 0; ks < 4; ks++) {
            const uint32_t ko = (uint32_t)ks * 32;
            uint32_t ah0[4], ah1[4];
            LDSM_X4(ah0, aH + ko);
            LDSM_X4(ah1, aH + 16 * ROWB + ko);
            uint32_t bhr[4][4], blr[4][4];
#pragma unroll
            for (int p = 0; p < 4; p++) {
                LDSM_X4(bhr[p], bH + (uint32_t)p * 16 * ROWB + ko);
                LDSM_X4(blr[p], bL + (uint32_t)p * 16 * ROWB + ko);
            }
            // 4 groups of 8 independent MMAs; same-acc reuse is 16 apart
#pragma unroll
            for (int j = 0; j < 8; j++)
                MMA_F16(acc[0][j], ah0, bhr[j >> 1][(j & 1) * 2], bhr[j >> 1][(j & 1) * 2 + 1]);
#pragma unroll
            for (int j = 0; j < 8; j++)
                MMA_F16(acc[1][j], ah1, bhr[j >> 1][(j & 1) * 2], bhr[j >> 1][(j & 1) * 2 + 1]);
#pragma unroll
            for (int j = 0; j < 8; j++)
                MMA_F16(acc[0][j], ah0, blr[j >> 1][(j & 1) * 2], blr[j >> 1][(j & 1) * 2 + 1]);
#pragma unroll
            for (int j = 0; j < 8; j++)
                MMA_F16(acc[1][j], ah1, blr[j >> 1][(j & 1) * 2], blr[j >> 1][(j & 1) * 2 + 1]);
        }
        __syncthreads();
    }

    // ---- epilogue ----
    const int rr = lane >> 2;
    const int cc = (lane & 3) * 2;
#pragma unroll
    for (int i = 0; i < 2; i++) {
#pragma unroll
        for (int j = 0; j < 8; j++) {
            const int row = m0 + i * 16 + rr;
            const int col = n0 + j * 8 + cc;
            if (EPI == 0) {
                float* p = Cf + (size_t)row * ldc + col;
                *(float2*)p = make_float2(acc[i][j][0] * outScale, acc[i][j][1] * outScale);
                *(float2*)(p + (size_t)8 * ldc) =
                    make_float2(acc[i][j][2] * outScale, acc[i][j][3] * outScale);
            } else {
                __half h0, l0, h1, l1;
                splitH(acc[i][j][0], h0, l0); splitH(acc[i][j][1], h1, l1);
                *(__half2*)(Ch + (size_t)row * ldc + col) = __halves2half2(h0, h1);
                *(__half2*)(Cl + (size_t)row * ldc + col) = __halves2half2(l0, l1);
                splitH(acc[i][j][2], h0, l0); splitH(acc[i][j][3], h1, l1);
                *(__half2*)(Ch + (size_t)(row + 8) * ldc + col) = __halves2half2(h0, h1);
                *(__half2*)(Cl + (size_t)(row + 8) * ldc + col) = __halves2half2(l0, l1);
            }
        }
    }
}

// ============================================================================
// fused conversion kernel: grid 10240 blocks x 256
// ============================================================================
__global__ void k_conv(const float* __restrict__ hid,
                       const float* __restrict__ qr,
                       const float* __restrict__ cb)
{
    __shared__ float ts[32][33];
    const int blk = blockIdx.x;
    const int tid = threadIdx.x;

    if (blk < 4096) {
        int idx = blk * 256 + tid;                       // 1M float4s
        float4 v = ((const float4*)hid)[idx];
        ((uint2*)g_Xnt_h)[idx] = pack4H(v);
    } else if (blk < 8192) {
        int i = blk - 4096;                              // 8 x 64 x 8
        int fb = i & 7, tb = (i >> 3) & 63, bq = i >> 9;
        int b = bq >> 2, q = bq & 3;
        int t0 = tb * 32, f0 = fb * 32;
        int tx = tid & 31, ty = tid >> 5;
#pragma unroll
        for (int r = 0; r < 4; r++) {
            int tt = t0 + ty + r * 8;
            ts[ty + r * 8][tx] = hid[(size_t)b * 2097152 + (size_t)tt * 1024 + q * 256 + f0 + tx];
        }
        __syncthreads();
#pragma unroll
        for (int r = 0; r < 4; r++) {
            int f = f0 + ty + r * 8;
            int tw = t0 + tx;
            __half h, l;
            splitH(ts[tx][ty + r * 8], h, l);
            size_t o = (size_t)bq * 524288 + (size_t)f * 2048 + tw;
            g_Xt_h[o] = h; g_Xt_l[o] = l;
        }
    } else if (blk < 9216) {
        int o4 = (blk - 8192) * 256 + tid;               // 262144 float4s
        int aq = o4 >> 14;
        int rem = (o4 << 2) & 65535;
        int e = rem >> 8, f = rem & 255;
        int a = aq >> 2, q = aq & 3;
        float4 v = *(const float4*)(qr + (size_t)a * 262144 + (size_t)e * 1024 + q * 256 + f);
        v.x *= 1024.f; v.y *= 1024.f; v.z *= 1024.f; v.w *= 1024.f;
        ((uint2*)g_Wc_h)[o4] = pack4H(v);
    } else {
        int i = blk - 9216;                              // 8 x 8 x 16
        int gpb = i & 7, gb = (i >> 3) & 7, aq = i >> 6;
        int a = aq >> 2, q = aq & 3;
        int g0 = gb * 32, gp0 = gpb * 32;
        int tx = tid & 31, ty = tid >> 5;
#pragma unroll
        for (int r = 0; r < 4; r++) {
            int g = g0 + ty + r * 8;
            ts[ty + r * 8][tx] =
                cb[(size_t)a * 262144 + (size_t)(q * 256 + g) * 256 + gp0 + tx] * 1024.f;
        }
        __syncthreads();
#pragma unroll
        for (int r = 0; r < 4; r++) {
            int gp = gp0 + ty + r * 8;
            int gw = g0 + tx;
            g_Ct_h[(size_t)aq * 65536 + (size_t)gp * 256 + gw] =
                __float2half_rn(ts[tx][ty + r * 8]);
        }
    }
}

// ---- reduce Gram partials (6 chunks, 3 tiles) + mirror + split fp16 ---------
// grid (16 sub, 3 tile, 8 bq), 256 threads; sub = 32x32 block of 128x128 tile.
// tile 0 -> G[0:128][0:128]; tile 1 -> G[0:128][128:256] AND its transpose
// into G[128:256][0:128]; tile 2 -> G[128:256][128:256].
__global__ void k_reduceG()
{
    __shared__ float s[32][33];
    const int sub = blockIdx.x, t = blockIdx.y, bq = blockIdx.z;
    const int r0 = (sub >> 2) * 32, c0 = (sub & 3) * 32;
    const int tx = threadIdx.x & 31, ty = threadIdx.x >> 5;

    const int br = (t == 2) ? 128 : 0;
    const int bc = (t == 0) ? 0 : 128;
    float v[4];
#pragma unroll
    for (int k = 0; k < 4; k++) {
        const int r = r0 + ty + k * 8;
        float a = 0.f;
#pragma unroll
        for (int ch = 0; ch < 6; ch++)
            a += g_Gpart[(size_t)((ch * 8 + bq) * 3 + t) * 16384 + r * 128 + c0 + tx];
        v[k] = a;
        s[ty + k * 8][tx] = a;
    }
#pragma unroll
    for (int k = 0; k < 4; k++) {
        __half h, l;
        splitH(v[k], h, l);
        size_t o = (size_t)bq * 65536 + (size_t)(br + r0 + ty + k * 8) * 256 + bc + c0 + tx;
        g_Gh[o] = h; g_Gl[o] = l;
    }
    if (t == 1) {
        __syncthreads();
#pragma unroll
        for (int k = 0; k < 4; k++) {
            const int orow = 128 + c0 + ty + k * 8;      // original col -> out row
            const int ocol = r0 + tx;                    // original row -> out col
            __half h, l;
            splitH(s[tx][ty + k * 8], h, l);
            size_t o = (size_t)bq * 65536 + (size_t)orow * 256 + ocol;
            g_Gh[o] = h; g_Gl[o] = l;
        }
    }
}

// ---- reduce Pq^T over q, descale 2^-10, split fp16 hi/lo --------------------
__global__ void k_reduceP()
{
    int i4 = blockIdx.x * 256 + threadIdx.x;             // 131072 float4s of P^T
    int ba = i4 >> 14;
    int off = i4 & 16383;
    int b = ba >> 2, a = ba & 3;
    size_t base = (size_t)(b * 16 + a * 4) * 16384 + off;
    float4 s = make_float4(0.f, 0.f, 0.f, 0.f);
#pragma unroll
    for (int q = 0; q < 4; q++) {
        float4 v = ((const float4*)g_Pq)[base + (size_t)q * 16384];
        s.x += v.x; s.y += v.y; s.z += v.z; s.w += v.w;
    }
    const float ds = 1.0f / 1024.0f;
    s.x *= ds; s.y *= ds; s.z *= ds; s.w *= ds;
    uint2 uh, ul;
    split4H(s, uh, ul);
    ((uint2*)g_Pt_h)[i4] = uh;
    ((uint2*)g_Pt_l)[i4] = ul;
}

// ============================================================================
// GEMM stage kernels
// ============================================================================
__global__ void __launch_bounds__(256, 1)
k_s1()  // Gram, symmetric: grid (tile 3, chunk 6, bq 8) = 144 CTAs
{
    const int t  = blockIdx.x;                 // 0:(0,0) 1:(0,1) 2:(1,1)
    const int ch = blockIdx.y, bq = blockIdx.z;
    const int mt = (t == 2) ? 1 : 0;
    const int nt = (t == 0) ? 0 : 1;
    const int k0 = (ch < 4) ? ch * 320 : 1280 + (ch - 4) * 384;
    const int K  = (ch < 4) ? 320 : 384;

    size_t xo = (size_t)bq * 524288;
    const __half* Ah = g_Xt_h + xo + (size_t)mt * 128 * 2048 + k0;
    const __half* Bh = g_Xt_h + xo + (size_t)nt * 128 * 2048 + k0;
    const __half* Bl = g_Xt_l + xo + (size_t)nt * 128 * 2048 + k0;
    float* Cf = g_Gpart + (size_t)((ch * 8 + bq) * 3 + t) * 16384;
    gemm_body<0>(Ah, 2048, Bh, Bl, 2048, K, Cf, nullptr, nullptr, 128, 1.0f);
}

__global__ void __launch_bounds__(256, 1)
k_s2()  // T = Ws @ G: grid (tile 4, 1, baq 32)
{
    int mt = blockIdx.x >> 1, nt = blockIdx.x & 1;
    int baq = blockIdx.z;
    int b = baq >> 4, a = (baq >> 2) & 3, q = baq & 3;
    const __half* Ah = g_Wc_h + (size_t)(a * 4 + q) * 65536 + (size_t)mt * 128 * 256;
    const __half* Bh = g_Gh + (size_t)(b * 4 + q) * 65536 + (size_t)nt * 128 * 256;
    const __half* Bl = g_Gl + (size_t)(b * 4 + q) * 65536 + (size_t)nt * 128 * 256;
    __half* Ch = g_Th + (size_t)baq * 65536 + (size_t)mt * 128 * 256 + nt * 128;
    __half* Cl = g_Tl + (size_t)baq * 65536 + (size_t)mt * 128 * 256 + nt * 128;
    gemm_body<1>(Ah, 256, Bh, Bl, 256, 256, nullptr, Ch, Cl, 256, 1.0f);
}

__global__ void __launch_bounds__(256, 1)
k_s3()  // Pq^T = Cs_t @ T^T
{
    int mt = blockIdx.x >> 1, nt = blockIdx.x & 1;
    int baq = blockIdx.z;
    int a = (baq >> 2) & 3, q = baq & 3;
    const __half* Ah = g_Ct_h + (size_t)(a * 4 + q) * 65536 + (size_t)mt * 128 * 256;
    const __half* Bh = g_Th + (size_t)baq * 65536 + (size_t)nt * 128 * 256;
    const __half* Bl = g_Tl + (size_t)baq * 65536 + (size_t)nt * 128 * 256;
    float* Cf = g_Pq + (size_t)baq * 65536 + (size_t)mt * 128 * 256 + nt * 128;
    gemm_body<0>(Ah, 256, Bh, Bl, 256, 256, Cf, nullptr, nullptr, 256, 1.0f);
}

__global__ void __launch_bounds__(256, 1)
k_s4(float* __restrict__ out)  // out = 2^-10 * X @ P
{
    int mt = blockIdx.x >> 1, nt = blockIdx.x & 1;
    int ba = blockIdx.z;
    int b = ba >> 2, a = ba & 3;
    const __half* Ah = g_Xnt_h + (size_t)b * 2097152 + (size_t)mt * 128 * 1024 + a * 256;
    const __half* Bh = g_Pt_h + (size_t)ba * 65536 + (size_t)nt * 128 * 256;
    const __half* Bl = g_Pt_l + (size_t)ba * 65536 + (size_t)nt * 128 * 256;
    float* Cf = out + (size_t)b * 2097152 + (size_t)mt * 128 * 1024 + a * 256 + nt * 128;
    gemm_body<0>(Ah, 1024, Bh, Bl, 256, 256, Cf, nullptr, nullptr, 1024, 1.0f / 1024.0f);
}

// ============================================================================
extern "C" void kernel_launch(void* const* d_in, const int* in_sizes, int n_in,
                              void* d_out, int out_size)
{
    const float* hidden    = (const float*)d_in[0];  // [2,2048,1024]
    const float* queries   = (const float*)d_in[1];  // [4,256,1024]
    const float* combiners = (const float*)d_in[2];  // [4,1024,256]
    float* out = (float*)d_out;
    (void)in_sizes; (void)n_in; (void)out_size;

    cudaFuncSetAttribute(k_s1, cudaFuncAttributeMaxDynamicSharedMemorySize, SMEM_DYN);
    cudaFuncSetAttribute(k_s2, cudaFuncAttributeMaxDynamicSharedMemorySize, SMEM_DYN);
    cudaFuncSetAttribute(k_s3, cudaFuncAttributeMaxDynamicSharedMemorySize, SMEM_DYN);
    cudaFuncSetAttribute(k_s4, cudaFuncAttributeMaxDynamicSharedMemorySize, SMEM_DYN);

    k_conv<<<10240, 256>>>(hidden, queries, combiners);
    k_s1<<<dim3(3, 6, 8), 256, SMEM_DYN>>>();
    k_reduceG<<<dim3(16, 3, 8), 256>>>();
    k_s2<<<dim3(4, 1, 32), 256, SMEM_DYN>>>();
    k_s3<<<dim3(4, 1, 32), 256, SMEM_DYN>>>();
    k_reduceP<<<512, 256>>>();
    k_s4<<<dim3(32, 1, 8), 256, SMEM_DYN>>>(out);
}